// round 4
// baseline (speedup 1.0000x reference)
#include <cuda_runtime.h>
#include <stdint.h>

// B=32, N=4096, D=768, n_take = int(4096*0.15)=614, p=0.8, key=(0,42).
#define BB 32
#define NN 4096
#define DD 768
#define NTAKE 614
#define NROWS (BB * NN)       // 131072
#define ROW4  (DD / 4)        // 192 float4 per row

// Per-(batch,patch) mask, recomputed deterministically every launch.
__device__ unsigned char g_mask[NROWS];

// ---------------- Threefry-2x32 (JAX-exact: 20 rounds, JAX key schedule) --------------
__device__ __forceinline__ uint2 tf2x32(uint32_t k0, uint32_t k1, uint32_t x0, uint32_t x1) {
    const uint32_t ks2 = k0 ^ k1 ^ 0x1BD11BDAu;
    x0 += k0; x1 += k1;
#define TF_RND(r) { x0 += x1; x1 = (x1 << (r)) | (x1 >> (32 - (r))); x1 ^= x0; }
    TF_RND(13) TF_RND(15) TF_RND(26) TF_RND(6)
    x0 += k1;  x1 += ks2 + 1u;
    TF_RND(17) TF_RND(29) TF_RND(16) TF_RND(24)
    x0 += ks2; x1 += k0 + 2u;
    TF_RND(13) TF_RND(15) TF_RND(26) TF_RND(6)
    x0 += k0;  x1 += k1 + 3u;
    TF_RND(17) TF_RND(29) TF_RND(16) TF_RND(24)
    x0 += k1;  x1 += ks2 + 4u;
    TF_RND(13) TF_RND(15) TF_RND(26) TF_RND(6)
    x0 += ks2; x1 += k0 + 5u;
#undef TF_RND
    return make_uint2(x0, x1);
}

__device__ __forceinline__ uint32_t rbits32(uint2 key, uint32_t i) {
    uint2 y = tf2x32(key.x, key.y, 0u, i);
    return y.x ^ y.y;
}
__device__ __forceinline__ uint2 splitk(uint2 key, uint32_t i) {
    return tf2x32(key.x, key.y, 0u, i);
}

// ---------------- Kernel 1: compute masks (1 block / batch, 1024 threads) -------------
// Stable sort via packed u64 (sortkey<<24 | pos<<12 | val): ordering by (key,pos)
// == lax.sort_key_val's stable sort by key.
__global__ void __launch_bounds__(1024) Masker_mask_kernel(float* __restrict__ mask_tail) {
    __shared__ unsigned long long arr[NN];
    const int b   = blockIdx.x;
    const int tid = threadIdx.x;

    uint2 kb    = tf2x32(0u, 42u, 0u, (uint32_t)b);   // split(key(42),32)[b]
    uint2 kperm = splitk(kb, 0u);
    uint2 kbern = splitk(kb, 1u);

    for (int i = tid; i < NN; i += blockDim.x) g_mask[b * NN + i] = 0;

    uint2 key = kperm;
    for (int r = 0; r < 2; r++) {
        uint2 nk = splitk(key, 0u);
        uint2 sk = splitk(key, 1u);
        key = nk;
        for (int i = tid; i < NN; i += blockDim.x) {
            uint32_t bits = rbits32(sk, (uint32_t)i);
            uint32_t val  = (r == 0) ? (uint32_t)i : (uint32_t)(arr[i] & 0xFFFu);
            arr[i] = ((unsigned long long)bits << 24) |
                     ((unsigned long long)(uint32_t)i << 12) |
                     (unsigned long long)val;
        }
        __syncthreads();
        for (unsigned k = 2; k <= NN; k <<= 1) {
            for (unsigned j = k >> 1; j > 0; j >>= 1) {
                #pragma unroll
                for (int t = 0; t < 2; t++) {
                    int i = tid + t * 1024;
                    unsigned ii = ((unsigned)i / j) * (2 * j) + ((unsigned)i % j);
                    unsigned pp = ii ^ j;   // pp > ii always
                    unsigned long long a = arr[ii], c = arr[pp];
                    bool up = ((ii & k) == 0u);
                    if ((a > c) == up) { arr[ii] = c; arr[pp] = a; }
                }
                __syncthreads();
            }
        }
    }

    for (int j = tid; j < NTAKE; j += blockDim.x) {
        uint32_t idx  = (uint32_t)(arr[j] & 0xFFFu);
        uint32_t bits = rbits32(kbern, (uint32_t)j);
        float u = __uint_as_float((bits >> 9) | 0x3F800000u) - 1.0f;
        if ((u < 0.8f) && (idx != 0u)) g_mask[b * NN + idx] = 1;
    }
    __syncthreads();

    if (mask_tail != nullptr) {
        for (int i = tid; i < NN; i += blockDim.x)
            mask_tail[(size_t)b * NN + i] = g_mask[b * NN + i] ? 1.0f : 0.0f;
    }
}

// ---------------- Kernel 2: zero only the masked rows (runs after join) ---------------
__global__ void __launch_bounds__(192) Masker_zero_kernel(float4* __restrict__ out) {
    const float4 z = make_float4(0.f, 0.f, 0.f, 0.f);
    for (int row = blockIdx.x; row < NROWS; row += gridDim.x) {
        if (g_mask[row]) {
            __stcs(out + (size_t)row * ROW4 + threadIdx.x, z);
        }
    }
}

extern "C" void kernel_launch(void* const* d_in, const int* in_sizes, int n_in,
                              void* d_out, int out_size) {
    const float* in = (const float*)d_in[0];
    float* out = (float*)d_out;

    const long long main_elems = (long long)BB * NN * DD;   // 100,663,296
    float* tail = nullptr;
    if ((long long)out_size >= main_elems + (long long)BB * NN)
        tail = out + main_elems;

    // Fork-join: mask kernel (SMs) on side stream overlaps the bulk D2D memcpy
    // (copy engine / driver copy path — no SM contention) on the origin stream.
    cudaStream_t s2 = nullptr;
    cudaEvent_t eFork = nullptr, eJoin = nullptr;
    bool forked = (cudaStreamCreateWithFlags(&s2, cudaStreamNonBlocking) == cudaSuccess) &&
                  (cudaEventCreateWithFlags(&eFork, cudaEventDisableTiming) == cudaSuccess) &&
                  (cudaEventCreateWithFlags(&eJoin, cudaEventDisableTiming) == cudaSuccess) &&
                  (cudaEventRecord(eFork, 0) == cudaSuccess) &&
                  (cudaStreamWaitEvent(s2, eFork, 0) == cudaSuccess);

    if (forked) {
        Masker_mask_kernel<<<BB, 1024, 0, s2>>>(tail);
        cudaMemcpyAsync(out, in, (size_t)main_elems * sizeof(float),
                        cudaMemcpyDeviceToDevice, 0);
        cudaEventRecord(eJoin, s2);
        cudaStreamWaitEvent(0, eJoin, 0);
    } else {
        Masker_mask_kernel<<<BB, 1024>>>(tail);
        cudaMemcpyAsync(out, in, (size_t)main_elems * sizeof(float),
                        cudaMemcpyDeviceToDevice, 0);
    }

    Masker_zero_kernel<<<2048, 192>>>((float4*)out);

    if (eFork) cudaEventDestroy(eFork);
    if (eJoin) cudaEventDestroy(eJoin);
    if (s2)    cudaStreamDestroy(s2);
}

// round 6
// speedup vs baseline: 1.3405x; 1.3405x over previous
#include <cuda_runtime.h>
#include <stdint.h>

// B=32, N=4096, D=768, n_take = int(4096*0.15)=614, p=0.8, key=(0,42).
#define BB 32
#define NN 4096
#define DD 768
#define NTAKE 614
#define NROWS (BB * NN)       // 131072
#define ROW4  (DD / 4)        // 192 float4 per row

// Compacted masked-row list: per-batch slots (<= NTAKE entries each) + count.
__device__ int g_list[BB * 1024];
__device__ int g_cnt[BB];

// ---------------- Threefry-2x32 (JAX-exact: 20 rounds, JAX key schedule) --------------
__device__ __forceinline__ uint2 tf2x32(uint32_t k0, uint32_t k1, uint32_t x0, uint32_t x1) {
    const uint32_t ks2 = k0 ^ k1 ^ 0x1BD11BDAu;
    x0 += k0; x1 += k1;
#define TF_RND(r) { x0 += x1; x1 = (x1 << (r)) | (x1 >> (32 - (r))); x1 ^= x0; }
    TF_RND(13) TF_RND(15) TF_RND(26) TF_RND(6)
    x0 += k1;  x1 += ks2 + 1u;
    TF_RND(17) TF_RND(29) TF_RND(16) TF_RND(24)
    x0 += ks2; x1 += k0 + 2u;
    TF_RND(13) TF_RND(15) TF_RND(26) TF_RND(6)
    x0 += k0;  x1 += k1 + 3u;
    TF_RND(17) TF_RND(29) TF_RND(16) TF_RND(24)
    x0 += k1;  x1 += ks2 + 4u;
    TF_RND(13) TF_RND(15) TF_RND(26) TF_RND(6)
    x0 += ks2; x1 += k0 + 5u;
#undef TF_RND
    return make_uint2(x0, x1);
}

__device__ __forceinline__ uint32_t rbits32(uint2 key, uint32_t i) {
    uint2 y = tf2x32(key.x, key.y, 0u, i);
    return y.x ^ y.y;
}
__device__ __forceinline__ uint2 splitk(uint2 key, uint32_t i) {
    return tf2x32(key.x, key.y, 0u, i);
}

// ---------------- Kernel 1: masks + compaction (1 block / batch, 1024 threads) --------
// Stable sort via packed u64 (sortkey<<24 | pos<<12 | val): ordering by (key,pos)
// == lax.sort_key_val's stable sort by key.
__global__ void __launch_bounds__(1024) Masker_mask_kernel(float* __restrict__ mask_tail) {
    __shared__ unsigned long long arr[NN];
    __shared__ unsigned char flags[NN];
    __shared__ int s_cnt;
    const int b   = blockIdx.x;
    const int tid = threadIdx.x;

    uint2 kb    = tf2x32(0u, 42u, 0u, (uint32_t)b);   // split(key(42),32)[b]
    uint2 kperm = splitk(kb, 0u);
    uint2 kbern = splitk(kb, 1u);

    for (int i = tid; i < NN; i += blockDim.x) flags[i] = 0;
    if (tid == 0) s_cnt = 0;

    uint2 key = kperm;
    for (int r = 0; r < 2; r++) {
        uint2 nk = splitk(key, 0u);
        uint2 sk = splitk(key, 1u);
        key = nk;
        for (int i = tid; i < NN; i += blockDim.x) {
            uint32_t bits = rbits32(sk, (uint32_t)i);
            uint32_t val  = (r == 0) ? (uint32_t)i : (uint32_t)(arr[i] & 0xFFFu);
            arr[i] = ((unsigned long long)bits << 24) |
                     ((unsigned long long)(uint32_t)i << 12) |
                     (unsigned long long)val;
        }
        __syncthreads();
        for (unsigned k = 2; k <= NN; k <<= 1) {
            for (unsigned j = k >> 1; j > 0; j >>= 1) {
                #pragma unroll
                for (int t = 0; t < 2; t++) {
                    int i = tid + t * 1024;
                    unsigned ii = ((unsigned)i / j) * (2 * j) + ((unsigned)i % j);
                    unsigned pp = ii ^ j;   // pp > ii always
                    unsigned long long a = arr[ii], c = arr[pp];
                    bool up = ((ii & k) == 0u);
                    if ((a > c) == up) { arr[ii] = c; arr[pp] = a; }
                }
                __syncthreads();
            }
        }
    }

    // scatter keep-flags (permutation -> idx values distinct, no write conflicts)
    for (int j = tid; j < NTAKE; j += blockDim.x) {
        uint32_t idx  = (uint32_t)(arr[j] & 0xFFFu);
        uint32_t bits = rbits32(kbern, (uint32_t)j);
        float u = __uint_as_float((bits >> 9) | 0x3F800000u) - 1.0f;
        if ((u < 0.8f) && (idx != 0u)) flags[idx] = 1;
    }
    __syncthreads();

    // compact masked indices into this batch's slot region + write mask tail
    for (int i = tid; i < NN; i += blockDim.x) {
        unsigned char f = flags[i];
        if (mask_tail != nullptr)
            mask_tail[(size_t)b * NN + i] = f ? 1.0f : 0.0f;
        if (f) {
            int pos = atomicAdd(&s_cnt, 1);
            g_list[b * 1024 + pos] = i;
        }
    }
    __syncthreads();
    if (tid == 0) g_cnt[b] = s_cnt;
}

// ---------------- Kernel 2: pure streaming copy (no mask dependency) ------------------
__global__ void __launch_bounds__(256) Masker_copy_kernel(const float4* __restrict__ in,
                                                          float4* __restrict__ out) {
    const int n4 = NROWS * ROW4;                 // 25,165,824
    const int stride = gridDim.x * blockDim.x;
    int i = blockIdx.x * blockDim.x + threadIdx.x;
    #pragma unroll 4
    for (; i < n4; i += stride) {
        __stcs(out + i, __ldcs(in + i));
    }
}

// ---------------- Kernel 3: zero only compacted masked rows ---------------------------
__global__ void __launch_bounds__(192) Masker_zero_kernel(float4* __restrict__ out) {
    const float4 z = make_float4(0.f, 0.f, 0.f, 0.f);
    const int G = gridDim.x;
    for (int b = 0; b < BB; b++) {
        int cnt = g_cnt[b];
        for (int j = blockIdx.x; j < cnt; j += G) {
            int row = b * NN + g_list[b * 1024 + j];
            __stcs(out + (size_t)row * ROW4 + threadIdx.x, z);
        }
    }
}

extern "C" void kernel_launch(void* const* d_in, const int* in_sizes, int n_in,
                              void* d_out, int out_size) {
    const float* in = (const float*)d_in[0];
    float* out = (float*)d_out;

    const long long main_elems = (long long)BB * NN * DD;   // 100,663,296
    float* tail = nullptr;
    if ((long long)out_size >= main_elems + (long long)BB * NN)
        tail = out + main_elems;

    // Fork-join: mask kernel on side stream overlaps the SM streaming copy on the
    // origin (capture) stream; join before the selective zero kernel.
    cudaStream_t s2 = nullptr;
    cudaEvent_t eFork = nullptr, eJoin = nullptr;
    bool forked = (cudaStreamCreateWithFlags(&s2, cudaStreamNonBlocking) == cudaSuccess) &&
                  (cudaEventCreateWithFlags(&eFork, cudaEventDisableTiming) == cudaSuccess) &&
                  (cudaEventCreateWithFlags(&eJoin, cudaEventDisableTiming) == cudaSuccess) &&
                  (cudaEventRecord(eFork, 0) == cudaSuccess) &&
                  (cudaStreamWaitEvent(s2, eFork, 0) == cudaSuccess);

    const int n4 = NROWS * ROW4;
    const int copyBlocks = (n4 / 4 + 255) / 256;   // 4 float4 per thread

    if (forked) {
        Masker_mask_kernel<<<BB, 1024, 0, s2>>>(tail);
        Masker_copy_kernel<<<copyBlocks, 256>>>((const float4*)in, (float4*)out);
        cudaEventRecord(eJoin, s2);
        cudaStreamWaitEvent(0, eJoin, 0);
    } else {
        Masker_mask_kernel<<<BB, 1024>>>(tail);
        Masker_copy_kernel<<<copyBlocks, 256>>>((const float4*)in, (float4*)out);
    }

    Masker_zero_kernel<<<1024, 192>>>((float4*)out);

    if (eFork) cudaEventDestroy(eFork);
    if (eJoin) cudaEventDestroy(eJoin);
    if (s2)    cudaStreamDestroy(s2);
}